// round 16
// baseline (speedup 1.0000x reference)
#include <cuda_runtime.h>
#include <cuda.h>
#include <cuda_fp16.h>
#include <cstdint>
#include <math.h>

#define D 768
#define B 512
#define NTOT (2 * D)            // 1536 rows of concatenated W

// GEMM tiling: CTA 128x128, 256 threads, warp tile 64x32; TK=64 fp16/stage
#define TM 128
#define TN 128
#define TK 64
#define STAGES 4
#define KSEG 256                // K per CTA (z in 0..2)
#define CHUNKS_PER (KSEG / TK)  // 4
#define NCTA 144                // (12, 4, 3) -> 1 CTA/SM
#define NTHREADS 256

#define STAGE_BYTES 32768       // A 16KB + B 16KB
#define SMEM_MBAR_OFF 640       // full[4] @640
#define SMEM_TILES_OFF 1024
#define SMEM_TOTAL (SMEM_TILES_OFF + STAGES * STAGE_BYTES)   // 132096

// ---------------------------------------------------------------------------
// Device scratch (allocation-free)
// ---------------------------------------------------------------------------
__device__ __half g_s16[B * D];
__device__ __half g_W16[NTOT * D];
__device__ float  g_logits[B * 2];
__device__ int    g_sync;

// ---------------------------------------------------------------------------
// PTX helpers (sm_80/sm_90 base features — legal on plain compute_103)
// ---------------------------------------------------------------------------
__device__ __forceinline__ uint32_t smem_u32(const void* p) {
    uint32_t a;
    asm("{ .reg .u64 t; cvta.to.shared.u64 t, %1; cvt.u32.u64 %0, t; }"
        : "=r"(a) : "l"(p));
    return a;
}

#define SWZ(o) ((o) ^ (((o) >> 3) & 0x70))

#define MBARRIER_INIT(addr, cnt) \
    asm volatile("mbarrier.init.shared.b64 [%0], %1;" :: "r"(addr), "r"(cnt) : "memory")
#define MBARRIER_EXPECT_TX(addr, bytes) \
    asm volatile("mbarrier.arrive.expect_tx.shared.b64 _, [%0], %1;" \
                 :: "r"(addr), "r"(bytes) : "memory")

__device__ __forceinline__ void mbar_wait(uint32_t mbar, uint32_t parity) {
    uint32_t done;
    asm volatile("{\n\t.reg .pred p;\n\t"
                 "mbarrier.try_wait.parity.acquire.cta.shared::cta.b64 p, [%1], %2;\n\t"
                 "selp.b32 %0, 1, 0, p;\n\t}"
                 : "=r"(done) : "r"(mbar), "r"(parity) : "memory");
    if (!done) {
        asm volatile("{\n\t.reg .pred P1;\n\t"
                     "WL_%=:\n\t"
                     "mbarrier.try_wait.parity.acquire.cta.shared::cta.b64 P1, [%0], %1, 0x989680;\n\t"
                     "@P1 bra.uni WD_%=;\n\t"
                     "bra.uni WL_%=;\n\t"
                     "WD_%=:\n\t}"
                     :: "r"(mbar), "r"(parity) : "memory");
    }
}

__device__ __forceinline__ void tma_load_2d(uint32_t dst, const CUtensorMap* map,
                                            int x, int y, uint32_t mbar) {
    asm volatile("cp.async.bulk.tensor.2d.shared::cta.global.tile.mbarrier::complete_tx::bytes "
                 "[%0], [%1, {%2, %3}], [%4];"
                 :: "r"(dst), "l"(map), "r"(x), "r"(y), "r"(mbar) : "memory");
}

#define LDSM_X4(r, addr) \
    asm volatile("ldmatrix.sync.aligned.m8n8.x4.shared.b16 {%0,%1,%2,%3}, [%4];" \
                 : "=r"((r)[0]), "=r"((r)[1]), "=r"((r)[2]), "=r"((r)[3]) \
                 : "r"(addr))

// fp16 MMA, fp32 accumulate
#define MMA_F16(d, a, b0, b1) \
    asm volatile("mma.sync.aligned.m16n8k16.row.col.f32.f16.f16.f32 " \
                 "{%0,%1,%2,%3}, {%4,%5,%6,%7}, {%8,%9}, {%0,%1,%2,%3};" \
                 : "+f"((d)[0]), "+f"((d)[1]), "+f"((d)[2]), "+f"((d)[3]) \
                 : "r"((a)[0]), "r"((a)[1]), "r"((a)[2]), "r"((a)[3]), \
                   "r"(b0), "r"(b1))

// ---------------------------------------------------------------------------
// Kernel 1: fp32 -> fp16 convert, 16 floats/thread (4x LDG.128 + 2x STG.128),
// 192 blocks x 512 threads (1.3 waves, high MLP). Also: logits = bias,
// g_sync = 0.
// ---------------------------------------------------------------------------
__global__ __launch_bounds__(512)
void quant_kernel(const float4* __restrict__ W4p,
                  const float4* __restrict__ S4p,
                  const float* __restrict__ fc_b) {
    const int WP = NTOT * D / 8;   // 147456 groups of 8 floats
    const int SP = B * D / 8;      // 49152
    int u = blockIdx.x * blockDim.x + threadIdx.x;   // 0..98303

    if (u == 0) g_sync = 0;
    if (u < B * 2) g_logits[u] = fc_b[u & 1];

#pragma unroll
    for (int half = 0; half < 2; half++) {
        int g = 2 * u + half;
        if (g >= WP + SP) break;

        float4 x0, x1;
        __half* dst;
        int e;
        if (g < WP) { x0 = W4p[2 * g]; x1 = W4p[2 * g + 1]; dst = g_W16; e = g * 8; }
        else {
            int q = g - WP;
            x0 = S4p[2 * q]; x1 = S4p[2 * q + 1]; dst = g_s16; e = q * 8;
        }

        __half2 h[4];
        h[0] = __float22half2_rn(make_float2(x0.x, x0.y));
        h[1] = __float22half2_rn(make_float2(x0.z, x0.w));
        h[2] = __float22half2_rn(make_float2(x1.x, x1.y));
        h[3] = __float22half2_rn(make_float2(x1.z, x1.w));
        *(uint4*)(dst + e) = make_uint4(*(uint32_t*)&h[0], *(uint32_t*)&h[1],
                                        *(uint32_t*)&h[2], *(uint32_t*)&h[3]);
    }
}

// ---------------------------------------------------------------------------
// Kernel 2: TMA-fed fp16 HMMA GEMM with register-prefetched V +
// v-dot reduce + device-wide barrier + softmax/fuse.
// Grid (12, 4, 3) = 144 CTAs, 256 threads. z = K segment (256 wide).
// TMA issuance spread across threads 0..3 (one chunk each).
// ---------------------------------------------------------------------------
__global__ __launch_bounds__(NTHREADS, 1)
void gemm_fuse_kernel(const float* __restrict__ V,
                      const float* __restrict__ S,
                      float* __restrict__ out,
                      const __grid_constant__ CUtensorMap map_s,
                      const __grid_constant__ CUtensorMap map_w) {
    extern __shared__ __align__(1024) char smem[];
    const uint32_t smem_base = smem_u32(smem);
    float* rowAcc = (float*)smem;               // 128 floats at offset 0

    const int tid  = threadIdx.x;
    const int wid  = tid >> 5;
    const int lane = tid & 31;
    const int warp_m = wid & 1;                 // 2 x 64 rows
    const int warp_n = wid >> 1;                // 4 x 32 cols

    const int colBase = blockIdx.x * TN;
    const int rowBase = blockIdx.y * TM;
    const int kOff0   = blockIdx.z * KSEG;

    const uint32_t fullBar = smem_base + SMEM_MBAR_OFF;   // 4 x 8B

    if (tid < TM) rowAcc[tid] = 0.0f;
    if (tid < STAGES) MBARRIER_INIT(fullBar + tid * 8, 1);
    __syncthreads();

    // issue all 4 chunks, one per thread (threads 0..3 of warp 0)
    if (tid < CHUNKS_PER) {
        const int p = tid;
        uint32_t mb  = fullBar + p * 8;
        uint32_t dst = smem_base + SMEM_TILES_OFF + p * STAGE_BYTES;
        MBARRIER_EXPECT_TX(mb, STAGE_BYTES);
        tma_load_2d(dst,         &map_s, kOff0 + p * TK, rowBase, mb);
        tma_load_2d(dst + 16384, &map_w, kOff0 + p * TK, colBase, mb);
    }

    // prefetch V fragments into registers: these 32 long-latency LDGs
    // overlap the TMA wait + entire MMA stream instead of trailing it
    const int iBase = (colBase % D) + 32 * warp_n;
    const int kIdx  = colBase / D;
    float2 vx[4][4][2];
#pragma unroll
    for (int mi = 0; mi < 4; mi++) {
        int r0 = rowBase + 64 * warp_m + 16 * mi + (lane >> 2);
#pragma unroll
        for (int nj = 0; nj < 4; nj++) {
            vx[mi][nj][0] = *(const float2*)(V + (size_t)r0 * D + iBase
                                             + 8 * nj + 2 * (lane & 3));
            vx[mi][nj][1] = *(const float2*)(V + (size_t)(r0 + 8) * D + iBase
                                             + 8 * nj + 2 * (lane & 3));
        }
    }

    float acc[4][4][4] = {};                    // [m16 tile][n8 tile][frag]

    const int rowA = lane & 15, colSelA = lane >> 4;
    const int rowB = ((lane >> 4) << 3) + (lane & 7), colSelB = (lane >> 3) & 1;

#pragma unroll
    for (int it = 0; it < CHUNKS_PER; it++) {
        mbar_wait(fullBar + it * 8, 0u);

        const uint32_t sA = smem_base + SMEM_TILES_OFF + it * STAGE_BYTES;
        const uint32_t sB = sA + 16384;

#pragma unroll
        for (int ks = 0; ks < 4; ks++) {
            uint32_t a[4][4];
            uint32_t b[2][4];
#pragma unroll
            for (int mi = 0; mi < 4; mi++) {
                uint32_t addr = sA + SWZ((64 * warp_m + 16 * mi + rowA) * 128
                                         + (2 * ks + colSelA) * 16);
                LDSM_X4(a[mi], addr);
            }
#pragma unroll
            for (int q = 0; q < 2; q++) {
                uint32_t addr = sB + SWZ((32 * warp_n + 16 * q + rowB) * 128
                                         + (2 * ks + colSelB) * 16);
                LDSM_X4(b[q], addr);
            }
#pragma unroll
            for (int mi = 0; mi < 4; mi++)
#pragma unroll
                for (int nj = 0; nj < 4; nj++) {
                    uint32_t b0 = b[nj >> 1][(nj & 1) * 2 + 0];
                    uint32_t b1 = b[nj >> 1][(nj & 1) * 2 + 1];
                    MMA_F16(acc[mi][nj], a[mi], b0, b1);
                }
        }
    }

    // --- epilogue 1: partial C . v_x (registers), reduce into logits ---
    float rs[4][2] = {};
#pragma unroll
    for (int mi = 0; mi < 4; mi++) {
#pragma unroll
        for (int nj = 0; nj < 4; nj++) {
            rs[mi][0] = fmaf(acc[mi][nj][0], vx[mi][nj][0].x, rs[mi][0]);
            rs[mi][0] = fmaf(acc[mi][nj][1], vx[mi][nj][0].y, rs[mi][0]);
            rs[mi][1] = fmaf(acc[mi][nj][2], vx[mi][nj][1].x, rs[mi][1]);
            rs[mi][1] = fmaf(acc[mi][nj][3], vx[mi][nj][1].y, rs[mi][1]);
        }
    }
#pragma unroll
    for (int mi = 0; mi < 4; mi++)
#pragma unroll
        for (int h = 0; h < 2; h++) {
            rs[mi][h] += __shfl_xor_sync(0xffffffff, rs[mi][h], 1);
            rs[mi][h] += __shfl_xor_sync(0xffffffff, rs[mi][h], 2);
        }
    if ((lane & 3) == 0) {
#pragma unroll
        for (int mi = 0; mi < 4; mi++) {
            int lr = 64 * warp_m + 16 * mi + (lane >> 2);
            atomicAdd(&rowAcc[lr],     rs[mi][0]);
            atomicAdd(&rowAcc[lr + 8], rs[mi][1]);
        }
    }
    __syncthreads();
    if (tid < TM)
        atomicAdd(&g_logits[(rowBase + tid) * 2 + kIdx], rowAcc[tid]);

    // --- device-wide barrier (144 CTAs, 1/SM: all co-resident) ---
    __threadfence();
    __syncthreads();
    if (tid == 0) {
        atomicAdd(&g_sync, 1);
        while (*(volatile int*)&g_sync != NCTA) { }
    }
    __syncthreads();
    __threadfence();

    // --- epilogue 2: softmax(2 logits) + fused combine, strided over grid ---
    const int ctaLin = (blockIdx.z * gridDim.y + blockIdx.y) * gridDim.x + blockIdx.x;
    const int gt = ctaLin * NTHREADS + tid;
    const int stride = NCTA * NTHREADS;         // 36864
#pragma unroll
    for (int i = 0; i < 3; i++) {
        int idx = gt + i * stride;
        if (idx >= B * D / 4) break;
        int b = idx / (D / 4);
        float l0 = g_logits[b * 2 + 0];
        float l1 = g_logits[b * 2 + 1];
        float mx = fmaxf(l0, l1);
        float e0 = expf(l0 - mx);
        float e1 = expf(l1 - mx);
        float inv = 1.0f / (e0 + e1);
        float wa = e0 * inv;
        float wb = e1 * inv;
        float4 v = ((const float4*)V)[idx];
        float4 s = ((const float4*)S)[idx];
        float4 o;
        o.x = wa * v.x + wb * s.x;
        o.y = wa * v.y + wb * s.y;
        o.z = wa * v.z + wb * s.z;
        o.w = wa * v.w + wb * s.w;
        ((float4*)out)[idx] = o;
    }
}

// ---------------------------------------------------------------------------
// Host: tensormap construction via driver entry point (no -lcuda needed)
// ---------------------------------------------------------------------------
typedef CUresult (*PFN_encodeTiled)(
    CUtensorMap*, CUtensorMapDataType, cuuint32_t, void*,
    const cuuint64_t*, const cuuint64_t*, const cuuint32_t*, const cuuint32_t*,
    CUtensorMapInterleave, CUtensorMapSwizzle, CUtensorMapL2promotion,
    CUtensorMapFloatOOBfill);

static void make_map(PFN_encodeTiled fn, CUtensorMap* m, void* base,
                     unsigned long long rows, unsigned int boxRows) {
    cuuint64_t gd[2] = {(cuuint64_t)D, (cuuint64_t)rows};
    cuuint64_t gs[1] = {(cuuint64_t)(D * 2)};     // row stride in bytes (fp16)
    cuuint32_t bd[2] = {64u, boxRows};            // 64 fp16 = 128 B inner box
    cuuint32_t es[2] = {1u, 1u};
    fn(m, CU_TENSOR_MAP_DATA_TYPE_FLOAT16, 2, base, gd, gs, bd, es,
       CU_TENSOR_MAP_INTERLEAVE_NONE, CU_TENSOR_MAP_SWIZZLE_128B,
       CU_TENSOR_MAP_L2_PROMOTION_L2_128B, CU_TENSOR_MAP_FLOAT_OOB_FILL_NONE);
}

extern "C" void kernel_launch(void* const* d_in, const int* in_sizes, int n_in,
                              void* d_out, int out_size) {
    const float* v_x  = (const float*)d_in[0];
    const float* s_x  = (const float*)d_in[1];
    const float* fc_w = (const float*)d_in[2];
    const float* fc_b = (const float*)d_in[3];
    float* out = (float*)d_out;

    cudaFuncSetAttribute(gemm_fuse_kernel,
                         cudaFuncAttributeMaxDynamicSharedMemorySize, SMEM_TOTAL);

    PFN_encodeTiled encode = nullptr;
    cudaDriverEntryPointQueryResult qres;
    cudaGetDriverEntryPoint("cuTensorMapEncodeTiled", (void**)&encode,
                            cudaEnableDefault, &qres);

    void *p_s16, *p_W16;
    cudaGetSymbolAddress(&p_s16, g_s16);
    cudaGetSymbolAddress(&p_W16, g_W16);

    CUtensorMap m_s, m_w;
    make_map(encode, &m_s, p_s16, B,    TM);
    make_map(encode, &m_w, p_W16, NTOT, TN);

    // 1) fp16 convert (16 floats/thread, 192 blocks) + bias init + sync reset
    quant_kernel<<<192, 512>>>((const float4*)fc_w, (const float4*)s_x, fc_b);

    // 2) TMA-fed fp16 HMMA GEMM (V in registers) + dot + barrier + fuse
    dim3 grid(NTOT / TN, B / TM, 3);   // (12, 4, 3) = 144 CTAs
    gemm_fuse_kernel<<<grid, NTHREADS, SMEM_TOTAL>>>(v_x, s_x, out, m_s, m_w);
}

// round 17
// speedup vs baseline: 1.1356x; 1.1356x over previous
#include <cuda_runtime.h>
#include <cuda.h>
#include <cuda_fp16.h>
#include <cstdint>
#include <math.h>

#define D 768
#define B 512
#define NTOT (2 * D)            // 1536 rows of concatenated W

// GEMM tiling: CTA 128x128, 256 threads, warp tile 64x32; TK=64 fp16/stage
#define TM 128
#define TN 128
#define TK 64
#define STAGES 4
#define KSEG 256                // K per CTA (z in 0..2)
#define CHUNKS_PER (KSEG / TK)  // 4
#define NCTA 144                // (12, 4, 3) -> 1 CTA/SM
#define NTHREADS 256

#define STAGE_BYTES 32768       // A 16KB + B 16KB
#define SMEM_MBAR_OFF 640       // full[4] @640
#define SMEM_TILES_OFF 1024
#define SMEM_TOTAL (SMEM_TILES_OFF + STAGES * STAGE_BYTES)   // 132096

// ---------------------------------------------------------------------------
// Device scratch (allocation-free)
// ---------------------------------------------------------------------------
__device__ __half g_s16[B * D];
__device__ __half g_W16[NTOT * D];
__device__ float  g_logits[B * 2];
__device__ int    g_sync;

// ---------------------------------------------------------------------------
// PTX helpers (sm_80/sm_90 base features — legal on plain compute_103)
// ---------------------------------------------------------------------------
__device__ __forceinline__ uint32_t smem_u32(const void* p) {
    uint32_t a;
    asm("{ .reg .u64 t; cvta.to.shared.u64 t, %1; cvt.u32.u64 %0, t; }"
        : "=r"(a) : "l"(p));
    return a;
}

#define SWZ(o) ((o) ^ (((o) >> 3) & 0x70))

#define MBARRIER_INIT(addr, cnt) \
    asm volatile("mbarrier.init.shared.b64 [%0], %1;" :: "r"(addr), "r"(cnt) : "memory")
#define MBARRIER_EXPECT_TX(addr, bytes) \
    asm volatile("mbarrier.arrive.expect_tx.shared.b64 _, [%0], %1;" \
                 :: "r"(addr), "r"(bytes) : "memory")

__device__ __forceinline__ void mbar_wait(uint32_t mbar, uint32_t parity) {
    uint32_t done;
    asm volatile("{\n\t.reg .pred p;\n\t"
                 "mbarrier.try_wait.parity.acquire.cta.shared::cta.b64 p, [%1], %2;\n\t"
                 "selp.b32 %0, 1, 0, p;\n\t}"
                 : "=r"(done) : "r"(mbar), "r"(parity) : "memory");
    if (!done) {
        asm volatile("{\n\t.reg .pred P1;\n\t"
                     "WL_%=:\n\t"
                     "mbarrier.try_wait.parity.acquire.cta.shared::cta.b64 P1, [%0], %1, 0x989680;\n\t"
                     "@P1 bra.uni WD_%=;\n\t"
                     "bra.uni WL_%=;\n\t"
                     "WD_%=:\n\t}"
                     :: "r"(mbar), "r"(parity) : "memory");
    }
}

__device__ __forceinline__ void tma_load_2d(uint32_t dst, const CUtensorMap* map,
                                            int x, int y, uint32_t mbar) {
    asm volatile("cp.async.bulk.tensor.2d.shared::cta.global.tile.mbarrier::complete_tx::bytes "
                 "[%0], [%1, {%2, %3}], [%4];"
                 :: "r"(dst), "l"(map), "r"(x), "r"(y), "r"(mbar) : "memory");
}

#define LDSM_X4(r, addr) \
    asm volatile("ldmatrix.sync.aligned.m8n8.x4.shared.b16 {%0,%1,%2,%3}, [%4];" \
                 : "=r"((r)[0]), "=r"((r)[1]), "=r"((r)[2]), "=r"((r)[3]) \
                 : "r"(addr))

// fp16 MMA, fp32 accumulate
#define MMA_F16(d, a, b0, b1) \
    asm volatile("mma.sync.aligned.m16n8k16.row.col.f32.f16.f16.f32 " \
                 "{%0,%1,%2,%3}, {%4,%5,%6,%7}, {%8,%9}, {%0,%1,%2,%3};" \
                 : "+f"((d)[0]), "+f"((d)[1]), "+f"((d)[2]), "+f"((d)[3]) \
                 : "r"((a)[0]), "r"((a)[1]), "r"((a)[2]), "r"((a)[3]), \
                   "r"(b0), "r"(b1))

// ---------------------------------------------------------------------------
// Kernel 1: fp32 -> fp16 convert (8 floats/thread, 128-bit stores).
// Balanced 768x256 grid (R16 showed fat/imbalanced grids regress).
// Also: logits = bias, g_sync = 0. Ends with PDL launch_dependents.
// ---------------------------------------------------------------------------
__global__ __launch_bounds__(256)
void quant_kernel(const float4* __restrict__ W4p,
                  const float4* __restrict__ S4p,
                  const float* __restrict__ fc_b) {
    const int WP = NTOT * D / 8;   // 147456
    const int SP = B * D / 8;      // 49152
    int g = blockIdx.x * blockDim.x + threadIdx.x;

    if (g == 0) g_sync = 0;
    if (g < B * 2) g_logits[g] = fc_b[g & 1];

    if (g < WP + SP) {
        float4 x0, x1;
        __half* dst;
        int e;
        if (g < WP) { x0 = W4p[2 * g]; x1 = W4p[2 * g + 1]; dst = g_W16; e = g * 8; }
        else {
            int q = g - WP;
            x0 = S4p[2 * q]; x1 = S4p[2 * q + 1]; dst = g_s16; e = q * 8;
        }

        __half2 h[4];
        h[0] = __float22half2_rn(make_float2(x0.x, x0.y));
        h[1] = __float22half2_rn(make_float2(x0.z, x0.w));
        h[2] = __float22half2_rn(make_float2(x1.x, x1.y));
        h[3] = __float22half2_rn(make_float2(x1.z, x1.w));
        *(uint4*)(dst + e) = make_uint4(*(uint32_t*)&h[0], *(uint32_t*)&h[1],
                                        *(uint32_t*)&h[2], *(uint32_t*)&h[3]);
    }

    // PDL: signal dependents may launch; our stores flush at exit
    asm volatile("griddepcontrol.launch_dependents;" ::: "memory");
}

// ---------------------------------------------------------------------------
// Kernel 2: TMA-fed fp16 HMMA GEMM with register-prefetched V +
// v-dot reduce + device-wide barrier + softmax/fuse.
// Launched with ProgrammaticStreamSerialization: the prologue (smem init,
// V prefetch — independent of quant's outputs) overlaps quant execution;
// griddepcontrol.wait gates the first dependent access (TMA of g_s16/g_W16).
// Grid (12, 4, 3) = 144 CTAs, 256 threads. z = K segment (256 wide).
// ---------------------------------------------------------------------------
__global__ __launch_bounds__(NTHREADS, 1)
void gemm_fuse_kernel(const float* __restrict__ V,
                      const float* __restrict__ S,
                      float* __restrict__ out,
                      const __grid_constant__ CUtensorMap map_s,
                      const __grid_constant__ CUtensorMap map_w) {
    extern __shared__ __align__(1024) char smem[];
    const uint32_t smem_base = smem_u32(smem);
    float* rowAcc = (float*)smem;               // 128 floats at offset 0

    const int tid  = threadIdx.x;
    const int wid  = tid >> 5;
    const int lane = tid & 31;
    const int warp_m = wid & 1;                 // 2 x 64 rows
    const int warp_n = wid >> 1;                // 4 x 32 cols

    const int colBase = blockIdx.x * TN;
    const int rowBase = blockIdx.y * TM;
    const int kOff0   = blockIdx.z * KSEG;

    const uint32_t fullBar = smem_base + SMEM_MBAR_OFF;   // 4 x 8B

    if (tid < TM) rowAcc[tid] = 0.0f;
    if (tid < STAGES) MBARRIER_INIT(fullBar + tid * 8, 1);
    __syncthreads();

    // prefetch V fragments into registers: independent of quant's outputs,
    // so it runs BEFORE the PDL wait and overlaps the producer kernel
    const int iBase = (colBase % D) + 32 * warp_n;
    const int kIdx  = colBase / D;
    float2 vx[4][4][2];
#pragma unroll
    for (int mi = 0; mi < 4; mi++) {
        int r0 = rowBase + 64 * warp_m + 16 * mi + (lane >> 2);
#pragma unroll
        for (int nj = 0; nj < 4; nj++) {
            vx[mi][nj][0] = *(const float2*)(V + (size_t)r0 * D + iBase
                                             + 8 * nj + 2 * (lane & 3));
            vx[mi][nj][1] = *(const float2*)(V + (size_t)(r0 + 8) * D + iBase
                                             + 8 * nj + 2 * (lane & 3));
        }
    }

    // PDL: block until quant_kernel's writes (g_s16/g_W16/g_logits/g_sync)
    // are visible, then start the dependent TMA traffic
    asm volatile("griddepcontrol.wait;" ::: "memory");

    // issue all 4 chunks up-front (4 buffers, 4 chunks)
    if (tid == 0) {
#pragma unroll
        for (int p = 0; p < CHUNKS_PER; p++) {
            uint32_t mb  = fullBar + p * 8;
            uint32_t dst = smem_base + SMEM_TILES_OFF + p * STAGE_BYTES;
            MBARRIER_EXPECT_TX(mb, STAGE_BYTES);
            tma_load_2d(dst,         &map_s, kOff0 + p * TK, rowBase, mb);
            tma_load_2d(dst + 16384, &map_w, kOff0 + p * TK, colBase, mb);
        }
    }

    float acc[4][4][4] = {};                    // [m16 tile][n8 tile][frag]

    const int rowA = lane & 15, colSelA = lane >> 4;
    const int rowB = ((lane >> 4) << 3) + (lane & 7), colSelB = (lane >> 3) & 1;

#pragma unroll
    for (int it = 0; it < CHUNKS_PER; it++) {
        mbar_wait(fullBar + it * 8, 0u);

        const uint32_t sA = smem_base + SMEM_TILES_OFF + it * STAGE_BYTES;
        const uint32_t sB = sA + 16384;

#pragma unroll
        for (int ks = 0; ks < 4; ks++) {
            uint32_t a[4][4];
            uint32_t b[2][4];
#pragma unroll
            for (int mi = 0; mi < 4; mi++) {
                uint32_t addr = sA + SWZ((64 * warp_m + 16 * mi + rowA) * 128
                                         + (2 * ks + colSelA) * 16);
                LDSM_X4(a[mi], addr);
            }
#pragma unroll
            for (int q = 0; q < 2; q++) {
                uint32_t addr = sB + SWZ((32 * warp_n + 16 * q + rowB) * 128
                                         + (2 * ks + colSelB) * 16);
                LDSM_X4(b[q], addr);
            }
#pragma unroll
            for (int mi = 0; mi < 4; mi++)
#pragma unroll
                for (int nj = 0; nj < 4; nj++) {
                    uint32_t b0 = b[nj >> 1][(nj & 1) * 2 + 0];
                    uint32_t b1 = b[nj >> 1][(nj & 1) * 2 + 1];
                    MMA_F16(acc[mi][nj], a[mi], b0, b1);
                }
        }
    }

    // --- epilogue 1: partial C . v_x (registers), reduce into logits ---
    float rs[4][2] = {};
#pragma unroll
    for (int mi = 0; mi < 4; mi++) {
#pragma unroll
        for (int nj = 0; nj < 4; nj++) {
            rs[mi][0] = fmaf(acc[mi][nj][0], vx[mi][nj][0].x, rs[mi][0]);
            rs[mi][0] = fmaf(acc[mi][nj][1], vx[mi][nj][0].y, rs[mi][0]);
            rs[mi][1] = fmaf(acc[mi][nj][2], vx[mi][nj][1].x, rs[mi][1]);
            rs[mi][1] = fmaf(acc[mi][nj][3], vx[mi][nj][1].y, rs[mi][1]);
        }
    }
#pragma unroll
    for (int mi = 0; mi < 4; mi++)
#pragma unroll
        for (int h = 0; h < 2; h++) {
            rs[mi][h] += __shfl_xor_sync(0xffffffff, rs[mi][h], 1);
            rs[mi][h] += __shfl_xor_sync(0xffffffff, rs[mi][h], 2);
        }
    if ((lane & 3) == 0) {
#pragma unroll
        for (int mi = 0; mi < 4; mi++) {
            int lr = 64 * warp_m + 16 * mi + (lane >> 2);
            atomicAdd(&rowAcc[lr],     rs[mi][0]);
            atomicAdd(&rowAcc[lr + 8], rs[mi][1]);
        }
    }
    __syncthreads();
    if (tid < TM)
        atomicAdd(&g_logits[(rowBase + tid) * 2 + kIdx], rowAcc[tid]);

    // --- device-wide barrier (144 CTAs, 1/SM: all co-resident) ---
    __threadfence();
    __syncthreads();
    if (tid == 0) {
        atomicAdd(&g_sync, 1);
        while (*(volatile int*)&g_sync != NCTA) { }
    }
    __syncthreads();
    __threadfence();

    // --- epilogue 2: softmax(2 logits) + fused combine, strided over grid ---
    const int ctaLin = (blockIdx.z * gridDim.y + blockIdx.y) * gridDim.x + blockIdx.x;
    const int gt = ctaLin * NTHREADS + tid;
    const int stride = NCTA * NTHREADS;         // 36864
#pragma unroll
    for (int i = 0; i < 3; i++) {
        int idx = gt + i * stride;
        if (idx >= B * D / 4) break;
        int b = idx / (D / 4);
        float l0 = g_logits[b * 2 + 0];
        float l1 = g_logits[b * 2 + 1];
        float mx = fmaxf(l0, l1);
        float e0 = expf(l0 - mx);
        float e1 = expf(l1 - mx);
        float inv = 1.0f / (e0 + e1);
        float wa = e0 * inv;
        float wb = e1 * inv;
        float4 v = ((const float4*)V)[idx];
        float4 s = ((const float4*)S)[idx];
        float4 o;
        o.x = wa * v.x + wb * s.x;
        o.y = wa * v.y + wb * s.y;
        o.z = wa * v.z + wb * s.z;
        o.w = wa * v.w + wb * s.w;
        ((float4*)out)[idx] = o;
    }
}

// ---------------------------------------------------------------------------
// Host: tensormap construction via driver entry point (no -lcuda needed)
// ---------------------------------------------------------------------------
typedef CUresult (*PFN_encodeTiled)(
    CUtensorMap*, CUtensorMapDataType, cuuint32_t, void*,
    const cuuint64_t*, const cuuint64_t*, const cuuint32_t*, const cuuint32_t*,
    CUtensorMapInterleave, CUtensorMapSwizzle, CUtensorMapL2promotion,
    CUtensorMapFloatOOBfill);

static void make_map(PFN_encodeTiled fn, CUtensorMap* m, void* base,
                     unsigned long long rows, unsigned int boxRows) {
    cuuint64_t gd[2] = {(cuuint64_t)D, (cuuint64_t)rows};
    cuuint64_t gs[1] = {(cuuint64_t)(D * 2)};     // row stride in bytes (fp16)
    cuuint32_t bd[2] = {64u, boxRows};            // 64 fp16 = 128 B inner box
    cuuint32_t es[2] = {1u, 1u};
    fn(m, CU_TENSOR_MAP_DATA_TYPE_FLOAT16, 2, base, gd, gs, bd, es,
       CU_TENSOR_MAP_INTERLEAVE_NONE, CU_TENSOR_MAP_SWIZZLE_128B,
       CU_TENSOR_MAP_L2_PROMOTION_L2_128B, CU_TENSOR_MAP_FLOAT_OOB_FILL_NONE);
}

extern "C" void kernel_launch(void* const* d_in, const int* in_sizes, int n_in,
                              void* d_out, int out_size) {
    const float* v_x  = (const float*)d_in[0];
    const float* s_x  = (const float*)d_in[1];
    const float* fc_w = (const float*)d_in[2];
    const float* fc_b = (const float*)d_in[3];
    float* out = (float*)d_out;

    cudaFuncSetAttribute(gemm_fuse_kernel,
                         cudaFuncAttributeMaxDynamicSharedMemorySize, SMEM_TOTAL);

    PFN_encodeTiled encode = nullptr;
    cudaDriverEntryPointQueryResult qres;
    cudaGetDriverEntryPoint("cuTensorMapEncodeTiled", (void**)&encode,
                            cudaEnableDefault, &qres);

    void *p_s16, *p_W16;
    cudaGetSymbolAddress(&p_s16, g_s16);
    cudaGetSymbolAddress(&p_W16, g_W16);

    CUtensorMap m_s, m_w;
    make_map(encode, &m_s, p_s16, B,    TM);
    make_map(encode, &m_w, p_W16, NTOT, TN);

    // 1) fp16 convert + bias init + sync reset (balanced 768x256 grid)
    quant_kernel<<<768, 256>>>((const float4*)fc_w, (const float4*)s_x, fc_b);

    // 2) PDL launch: gemm prologue overlaps quant execution
    cudaLaunchConfig_t cfg = {};
    cfg.gridDim  = dim3(NTOT / TN, B / TM, 3);   // (12, 4, 3) = 144 CTAs
    cfg.blockDim = dim3(NTHREADS, 1, 1);
    cfg.dynamicSmemBytes = SMEM_TOTAL;
    cfg.stream = 0;
    cudaLaunchAttribute attrs[1];
    attrs[0].id = cudaLaunchAttributeProgrammaticStreamSerialization;
    attrs[0].val.programmaticStreamSerializationAllowed = 1;
    cfg.attrs = attrs;
    cfg.numAttrs = 1;
    cudaLaunchKernelEx(&cfg, gemm_fuse_kernel, v_x, s_x, out, m_s, m_w);
}